// round 6
// baseline (speedup 1.0000x reference)
#include <cuda_runtime.h>
#include <math.h>

#define NLINKS   4096
#define PMAXF    0.1f
#define BUDGETF  100.0f
#define THREADS  256
#define VPT      16        // 256*16 = 4096
#define PLO      0.5f      // probe bracket low
#define PHI      0.9f      // probe bracket high
#define HB       1.0f      // saturation boundary (>= HB -> contributes PMAX for tau<=PHI)
#define CAP1     768       // stage-1 active capacity (3KB smem), band ~614±23 -> 6.7 sigma
#define SLOTS1   3         // CAP1/THREADS
#define CAP2     256       // stage-2 active capacity
#define SLOTS2   8         // CAP2/32
#define NA       5         // block bisection iters (0.4 -> 0.0125)
#define NB       13        // per-warp bisection iters (0.0125 -> 1.5e-6)
#define NFALL    26        // fallback bisection iters
#define SENT     -1.0e30f

__device__ __forceinline__ float clipP(float t) {
    return fminf(fmaxf(t, 0.0f), PMAXF);
}

__global__ __launch_bounds__(THREADS, 8)
void proj_kernel(const float* __restrict__ raw, float* __restrict__ out, int nrows) {
    __shared__ float sAct[CAP1];
    __shared__ float sP[16];     // partials, two banks of 8
    __shared__ float sQ[16];
    __shared__ int   sCnt;
    __shared__ int   sCnt2;

    const int row = blockIdx.x;
    if (row >= nrows) return;

    const float*  rp  = raw + (size_t)row * NLINKS;
    float*        op  = out + (size_t)row * NLINKS;
    const float4* rp4 = reinterpret_cast<const float4*>(rp);
    float4*       op4 = reinterpret_cast<float4*>(op);

    const int tid  = threadIdx.x;
    const int lane = tid & 31;
    const int warp = tid >> 5;

    if (tid == 0) { sCnt = 0; sCnt2 = 0; }
    // sentinel-prefill stage-1 region; ordering vs compaction writes is covered
    // by the init-reduction barrier below
    #pragma unroll
    for (int j = 0; j < SLOTS1; j++) sAct[tid + j * THREADS] = SENT;

    float tau  = 0.0f;
    bool  done = false;

    {
        // ---- pass 1: load row (transient regs), g(0), band count ----
        float v[VPT];
        #pragma unroll
        for (int i = 0; i < VPT / 4; i++) {
            float4 q = rp4[tid + i * THREADS];
            v[4*i+0] = q.x; v[4*i+1] = q.y; v[4*i+2] = q.z; v[4*i+3] = q.w;
        }

        float s0 = 0.0f, cHigh = 0.0f;
        int nact = 0;
        #pragma unroll
        for (int i = 0; i < VPT; i++) {
            const float x = v[i];
            s0 += clipP(x);
            nact  += ((x > PLO) && (x < HB)) ? 1 : 0;
            cHigh += (x >= HB) ? 1.0f : 0.0f;
        }
        #pragma unroll
        for (int o = 16; o > 0; o >>= 1) {
            s0    += __shfl_xor_sync(0xffffffffu, s0, o);
            cHigh += __shfl_xor_sync(0xffffffffu, cHigh, o);
        }
        if (lane == 0) { sP[warp] = s0; sQ[warp] = cHigh; }
        __syncthreads();

        float g0 = 0.0f, Ch = 0.0f;
        #pragma unroll
        for (int w = 0; w < 8; w++) { g0 += sP[w]; Ch += sQ[w]; }

        if (g0 <= BUDGETF) {
            done = true;   // tau = 0: output is clip(x - 0, 0, PMAX) == clip(x)
        } else {
            // ---- stage-1 compaction of band (PLO, HB) into smem ----
            int inc = nact;
            #pragma unroll
            for (int o = 1; o < 32; o <<= 1) {
                int t = __shfl_up_sync(0xffffffffu, inc, o);
                if (lane >= o) inc += t;
            }
            const int excl = inc - nact;
            const int wtot = __shfl_sync(0xffffffffu, inc, 31);
            int wbase = 0;
            if (lane == 0) wbase = atomicAdd(&sCnt, wtot);
            wbase = __shfl_sync(0xffffffffu, wbase, 0);
            int idx = wbase + excl;
            #pragma unroll
            for (int i = 0; i < VPT; i++) {
                const float x = v[i];
                if ((x > PLO) && (x < HB)) {
                    if (idx < CAP1) sAct[idx] = x;
                    idx++;
                }
            }
            __syncthreads();
            const int nAct = sCnt;

            if (nAct <= CAP1) {
                float a[SLOTS1];
                #pragma unroll
                for (int j = 0; j < SLOTS1; j++) a[j] = sAct[tid + j * THREADS];
                const float C = Ch * PMAXF;

                // bracket verify: g(PLO) >= B >= g(PHI)
                float sL = 0.0f, sH = 0.0f;
                #pragma unroll
                for (int j = 0; j < SLOTS1; j++) {
                    sL += clipP(a[j] - PLO);
                    sH += clipP(a[j] - PHI);
                }
                #pragma unroll
                for (int o = 16; o > 0; o >>= 1) {
                    sL += __shfl_xor_sync(0xffffffffu, sL, o);
                    sH += __shfl_xor_sync(0xffffffffu, sH, o);
                }
                if (lane == 0) { sP[8 + warp] = sL; sQ[8 + warp] = sH; }
                __syncthreads();
                float gL = C, gH = C;
                #pragma unroll
                for (int w = 0; w < 8; w++) { gL += sP[8 + w]; gH += sQ[8 + w]; }

                if (gL >= BUDGETF && gH <= BUDGETF) {
                    // sentinel-refill stage-2 region; ordering vs recompact writes
                    // is covered by stage-A barriers
                    sAct[tid] = SENT;

                    float lo = PLO, hi = PHI;

                    // ---- stage A: block bisection on 3-slot active set ----
                    #pragma unroll 1
                    for (int it = 0; it < NA; it++) {
                        const float mid = 0.5f * (lo + hi);
                        float s = 0.0f;
                        #pragma unroll
                        for (int j = 0; j < SLOTS1; j++) s += clipP(a[j] - mid);
                        #pragma unroll
                        for (int o = 16; o > 0; o >>= 1)
                            s += __shfl_xor_sync(0xffffffffu, s, o);
                        const int slot = it & 1;
                        if (lane == 0) sP[slot * 8 + warp] = s;
                        __syncthreads();
                        float g = C;
                        #pragma unroll
                        for (int w = 0; w < 8; w++) g += sP[slot * 8 + w];
                        if (g > BUDGETF) lo = mid; else hi = mid;
                    }

                    // ---- recompact to stage-2 set: band (lo, hi + PMAX) ----
                    int nact2 = 0;
                    float cHigh2 = 0.0f;
                    #pragma unroll
                    for (int j = 0; j < SLOTS1; j++) {
                        const float x = a[j];
                        nact2  += ((x > lo) && ((x - hi) < PMAXF)) ? 1 : 0;
                        cHigh2 += (((x - hi) >= PMAXF) && (x > SENT)) ? 1.0f : 0.0f;
                    }
                    int inc2 = nact2;
                    #pragma unroll
                    for (int o = 1; o < 32; o <<= 1) {
                        int t = __shfl_up_sync(0xffffffffu, inc2, o);
                        if (lane >= o) inc2 += t;
                    }
                    const int excl2 = inc2 - nact2;
                    const int wtot2 = __shfl_sync(0xffffffffu, inc2, 31);
                    float cw = cHigh2;
                    #pragma unroll
                    for (int o = 16; o > 0; o >>= 1)
                        cw += __shfl_xor_sync(0xffffffffu, cw, o);
                    int wbase2 = 0;
                    if (lane == 0) wbase2 = atomicAdd(&sCnt2, wtot2);
                    wbase2 = __shfl_sync(0xffffffffu, wbase2, 0);
                    int idx2 = wbase2 + excl2;
                    #pragma unroll
                    for (int j = 0; j < SLOTS1; j++) {
                        const float x = a[j];
                        if ((x > lo) && ((x - hi) < PMAXF)) {
                            if (idx2 < CAP2) sAct[idx2] = x;
                            idx2++;
                        }
                    }
                    if (lane == 0) sQ[warp] = cw;
                    __syncthreads();
                    const int nAct2 = sCnt2;
                    float C2 = C;
                    #pragma unroll
                    for (int w = 0; w < 8; w++) C2 += sQ[w] * PMAXF;

                    if (nAct2 <= CAP2) {
                        // ---- stage B: every warp redundantly, no barriers after ----
                        float b[SLOTS2];
                        #pragma unroll
                        for (int k = 0; k < SLOTS2; k++) b[k] = sAct[lane + k * 32];

                        float blo = lo, bhi = hi;
                        #pragma unroll 1
                        for (int it = 0; it < NB; it++) {
                            const float mid = 0.5f * (blo + bhi);
                            float s = 0.0f;
                            #pragma unroll
                            for (int k = 0; k < SLOTS2; k++) s += clipP(b[k] - mid);
                            #pragma unroll
                            for (int o = 16; o > 0; o >>= 1)
                                s += __shfl_xor_sync(0xffffffffu, s, o);
                            if (C2 + s > BUDGETF) blo = mid; else bhi = mid;
                        }
                        const float tau0 = 0.5f * (blo + bhi);

                        // Newton correction (exact within the linear piece)
                        float gs = 0.0f, cnt = 0.0f;
                        #pragma unroll
                        for (int k = 0; k < SLOTS2; k++) {
                            const float t = b[k] - tau0;
                            gs  += clipP(t);
                            cnt += (t > 0.0f && t < PMAXF) ? 1.0f : 0.0f;
                        }
                        #pragma unroll
                        for (int o = 16; o > 0; o >>= 1) {
                            gs  += __shfl_xor_sync(0xffffffffu, gs, o);
                            cnt += __shfl_xor_sync(0xffffffffu, cnt, o);
                        }
                        tau  = tau0 + (C2 + gs - BUDGETF) / fmaxf(cnt, 1.0f);
                        done = true;
                    }
                }
            }
        }
    }   // v[] dead here

    // ---- fallback: full-row bisection, streaming from L1 (rare inputs) ----
    if (!done) {
        float vmin = 1e30f, vmax = -1e30f;
        #pragma unroll
        for (int i = 0; i < VPT / 4; i++) {
            float4 q = rp4[tid + i * THREADS];
            vmin = fminf(fminf(vmin, fminf(q.x, q.y)), fminf(q.z, q.w));
            vmax = fmaxf(fmaxf(vmax, fmaxf(q.x, q.y)), fmaxf(q.z, q.w));
        }
        #pragma unroll
        for (int o = 16; o > 0; o >>= 1) {
            vmin = fminf(vmin, __shfl_xor_sync(0xffffffffu, vmin, o));
            vmax = fmaxf(vmax, __shfl_xor_sync(0xffffffffu, vmax, o));
        }
        if (lane == 0) { sP[warp] = vmin; sQ[warp] = vmax; }
        __syncthreads();
        float lo = 1e30f, hi = -1e30f;
        #pragma unroll
        for (int w = 0; w < 8; w++) {
            lo = fminf(lo, sP[w]);
            hi = fmaxf(hi, sQ[w]);
        }
        lo -= PMAXF;

        #pragma unroll 1
        for (int it = 0; it < NFALL; it++) {
            const float mid = 0.5f * (lo + hi);
            float s = 0.0f;
            #pragma unroll
            for (int i = 0; i < VPT / 4; i++) {
                float4 q = rp4[tid + i * THREADS];
                s += clipP(q.x - mid) + clipP(q.y - mid)
                   + clipP(q.z - mid) + clipP(q.w - mid);
            }
            #pragma unroll
            for (int o = 16; o > 0; o >>= 1) s += __shfl_xor_sync(0xffffffffu, s, o);
            const int slot = (it + 1) & 1;
            if (lane == 0) sP[slot * 8 + warp] = s;
            __syncthreads();
            float g = 0.0f;
            #pragma unroll
            for (int w = 0; w < 8; w++) g += sP[slot * 8 + w];
            if (g > BUDGETF) lo = mid; else hi = mid;
        }
        const float tau0 = 0.5f * (lo + hi);

        float gs = 0.0f, cnt = 0.0f;
        #pragma unroll
        for (int i = 0; i < VPT / 4; i++) {
            float4 q = rp4[tid + i * THREADS];
            const float t0 = q.x - tau0, t1 = q.y - tau0, t2 = q.z - tau0, t3 = q.w - tau0;
            gs  += clipP(t0) + clipP(t1) + clipP(t2) + clipP(t3);
            cnt += ((t0 > 0.0f && t0 < PMAXF) ? 1.0f : 0.0f)
                 + ((t1 > 0.0f && t1 < PMAXF) ? 1.0f : 0.0f)
                 + ((t2 > 0.0f && t2 < PMAXF) ? 1.0f : 0.0f)
                 + ((t3 > 0.0f && t3 < PMAXF) ? 1.0f : 0.0f);
        }
        #pragma unroll
        for (int o = 16; o > 0; o >>= 1) {
            gs  += __shfl_xor_sync(0xffffffffu, gs, o);
            cnt += __shfl_xor_sync(0xffffffffu, cnt, o);
        }
        if (lane == 0) { sP[8 + warp] = gs; sQ[8 + warp] = cnt; }
        __syncthreads();
        float gsum = 0.0f, csum = 0.0f;
        #pragma unroll
        for (int w = 0; w < 8; w++) { gsum += sP[8 + w]; csum += sQ[8 + w]; }
        tau = tau0 + (gsum - BUDGETF) / fmaxf(csum, 1.0f);
    }

    // ---- final pass: re-read row (L1-resident) and write projection ----
    #pragma unroll
    for (int i = 0; i < VPT / 4; i++) {
        float4 q = rp4[tid + i * THREADS];
        float4 r;
        r.x = clipP(q.x - tau);
        r.y = clipP(q.y - tau);
        r.z = clipP(q.z - tau);
        r.w = clipP(q.w - tau);
        op4[tid + i * THREADS] = r;
    }
}

extern "C" void kernel_launch(void* const* d_in, const int* in_sizes, int n_in,
                              void* d_out, int out_size) {
    const float* raw = (const float*)d_in[0];
    float*       out = (float*)d_out;
    const int nrows = in_sizes[0] / NLINKS;
    proj_kernel<<<nrows, THREADS>>>(raw, out, nrows);
}

// round 7
// speedup vs baseline: 1.1335x; 1.1335x over previous
#include <cuda_runtime.h>
#include <math.h>

#define NLINKS   4096
#define PMAXF    0.1f
#define BUDGETF  100.0f
#define THREADS  256
#define VPT      16        // 256*16 = 4096
#define PLO      0.54f     // probe bracket low  (tau ~ 0.645 +/- 0.021 -> 5 sigma)
#define PHI      0.75f     // probe bracket high (5 sigma)
#define HB       0.85f     // saturation boundary (= PHI + PMAX)
#define CAP1     512       // stage-1 active capacity (2KB smem); band ~397+/-19 -> 6 sigma
#define SLOTS1   2         // CAP1/THREADS
#define CAP2     256       // stage-2 active capacity
#define SLOTS2   8         // CAP2/32
#define NA       4         // block bisection iters (0.21 -> 0.0131)
#define NB       11        // warp0 bisection iters (0.0131 -> 6.4e-6)
#define NFALL    26        // fallback bisection iters
#define SENT     -1.0e30f

__device__ __forceinline__ float clipP(float t) {
    return fminf(fmaxf(t, 0.0f), PMAXF);
}

__global__ __launch_bounds__(THREADS, 8)
void proj_kernel(const float* __restrict__ raw, float* __restrict__ out, int nrows) {
    __shared__ float sAct[CAP1];
    __shared__ float sP[16];     // partials, two banks of 8
    __shared__ float sQ[16];
    __shared__ float sTau;
    __shared__ int   sCnt;
    __shared__ int   sCnt2;

    const int row = blockIdx.x;
    if (row >= nrows) return;

    const float*  rp  = raw + (size_t)row * NLINKS;
    float*        op  = out + (size_t)row * NLINKS;
    const float4* rp4 = reinterpret_cast<const float4*>(rp);
    float4*       op4 = reinterpret_cast<float4*>(op);

    const int tid  = threadIdx.x;
    const int lane = tid & 31;
    const int warp = tid >> 5;

    if (tid == 0) { sCnt = 0; sCnt2 = 0; }
    // sentinel-prefill stage-1 region (ordering vs compaction writes covered
    // by the init-reduction barrier)
    #pragma unroll
    for (int j = 0; j < SLOTS1; j++) sAct[tid + j * THREADS] = SENT;

    float tau  = 0.0f;
    bool  done = false;
    bool  feas = false;

    {
        // ---- pass 1: load row (transient regs), g(0), band count ----
        float v[VPT];
        #pragma unroll
        for (int i = 0; i < VPT / 4; i++) {
            float4 q = rp4[tid + i * THREADS];
            v[4*i+0] = q.x; v[4*i+1] = q.y; v[4*i+2] = q.z; v[4*i+3] = q.w;
        }

        float s0 = 0.0f, cHigh = 0.0f;
        int nact = 0;
        #pragma unroll
        for (int i = 0; i < VPT; i++) {
            const float x = v[i];
            s0 += clipP(x);
            nact  += ((x > PLO) && (x < HB)) ? 1 : 0;
            cHigh += (x >= HB) ? 1.0f : 0.0f;
        }
        #pragma unroll
        for (int o = 16; o > 0; o >>= 1) {
            s0    += __shfl_xor_sync(0xffffffffu, s0, o);
            cHigh += __shfl_xor_sync(0xffffffffu, cHigh, o);
        }
        if (lane == 0) { sP[warp] = s0; sQ[warp] = cHigh; }
        __syncthreads();

        float g0 = 0.0f, Ch = 0.0f;
        #pragma unroll
        for (int w = 0; w < 8; w++) { g0 += sP[w]; Ch += sQ[w]; }

        if (g0 <= BUDGETF) {
            done = true; feas = true;   // tau = 0: clip(x) is the answer
        } else {
            // ---- stage-1 compaction of band (PLO, HB) into smem ----
            int inc = nact;
            #pragma unroll
            for (int o = 1; o < 32; o <<= 1) {
                int t = __shfl_up_sync(0xffffffffu, inc, o);
                if (lane >= o) inc += t;
            }
            const int excl = inc - nact;
            const int wtot = __shfl_sync(0xffffffffu, inc, 31);
            int wbase = 0;
            if (lane == 0) wbase = atomicAdd(&sCnt, wtot);
            wbase = __shfl_sync(0xffffffffu, wbase, 0);
            int idx = wbase + excl;
            #pragma unroll
            for (int i = 0; i < VPT; i++) {
                const float x = v[i];
                if ((x > PLO) && (x < HB)) {
                    if (idx < CAP1) sAct[idx] = x;
                    idx++;
                }
            }
            __syncthreads();
            const int nAct = sCnt;

            if (nAct <= CAP1) {
                float a[SLOTS1];
                #pragma unroll
                for (int j = 0; j < SLOTS1; j++) a[j] = sAct[tid + j * THREADS];
                const float C = Ch * PMAXF;

                // bracket verify: g(PLO) >= B >= g(PHI)
                float sL = 0.0f, sH = 0.0f;
                #pragma unroll
                for (int j = 0; j < SLOTS1; j++) {
                    sL += clipP(a[j] - PLO);
                    sH += clipP(a[j] - PHI);
                }
                #pragma unroll
                for (int o = 16; o > 0; o >>= 1) {
                    sL += __shfl_xor_sync(0xffffffffu, sL, o);
                    sH += __shfl_xor_sync(0xffffffffu, sH, o);
                }
                if (lane == 0) { sP[8 + warp] = sL; sQ[8 + warp] = sH; }
                __syncthreads();
                float gL = C, gH = C;
                #pragma unroll
                for (int w = 0; w < 8; w++) { gL += sP[8 + w]; gH += sQ[8 + w]; }

                if (gL >= BUDGETF && gH <= BUDGETF) {
                    // sentinel-refill stage-2 region (ordering covered by
                    // stage-A barriers before recompact writes land)
                    sAct[tid] = SENT;

                    float lo = PLO, hi = PHI;

                    // ---- stage A: block bisection on 2-slot active set ----
                    #pragma unroll 1
                    for (int it = 0; it < NA; it++) {
                        const float mid = 0.5f * (lo + hi);
                        float s = 0.0f;
                        #pragma unroll
                        for (int j = 0; j < SLOTS1; j++) s += clipP(a[j] - mid);
                        #pragma unroll
                        for (int o = 16; o > 0; o >>= 1)
                            s += __shfl_xor_sync(0xffffffffu, s, o);
                        const int slot = it & 1;
                        if (lane == 0) sP[slot * 8 + warp] = s;
                        __syncthreads();
                        float g = C;
                        #pragma unroll
                        for (int w = 0; w < 8; w++) g += sP[slot * 8 + w];
                        if (g > BUDGETF) lo = mid; else hi = mid;
                    }

                    // ---- recompact to stage-2 set: band (lo, hi + PMAX) ----
                    int nact2 = 0;
                    float cHigh2 = 0.0f;
                    #pragma unroll
                    for (int j = 0; j < SLOTS1; j++) {
                        const float x = a[j];
                        nact2  += ((x > lo) && ((x - hi) < PMAXF)) ? 1 : 0;
                        cHigh2 += ((x - hi) >= PMAXF) ? 1.0f : 0.0f;
                    }
                    int inc2 = nact2;
                    #pragma unroll
                    for (int o = 1; o < 32; o <<= 1) {
                        int t = __shfl_up_sync(0xffffffffu, inc2, o);
                        if (lane >= o) inc2 += t;
                    }
                    const int excl2 = inc2 - nact2;
                    const int wtot2 = __shfl_sync(0xffffffffu, inc2, 31);
                    float cw = cHigh2;
                    #pragma unroll
                    for (int o = 16; o > 0; o >>= 1)
                        cw += __shfl_xor_sync(0xffffffffu, cw, o);
                    int wbase2 = 0;
                    if (lane == 0) wbase2 = atomicAdd(&sCnt2, wtot2);
                    wbase2 = __shfl_sync(0xffffffffu, wbase2, 0);
                    int idx2 = wbase2 + excl2;
                    #pragma unroll
                    for (int j = 0; j < SLOTS1; j++) {
                        const float x = a[j];
                        if ((x > lo) && ((x - hi) < PMAXF)) {
                            if (idx2 < CAP2) sAct[idx2] = x;
                            idx2++;
                        }
                    }
                    if (lane == 0) sQ[warp] = cw;
                    __syncthreads();
                    const int nAct2 = sCnt2;
                    float C2 = C;
                    #pragma unroll
                    for (int w = 0; w < 8; w++) C2 += sQ[w] * PMAXF;

                    if (nAct2 <= CAP2) {
                        // ---- stage B: warp 0 only; other warps go wait at the
                        // sTau barrier and issue nothing ----
                        if (warp == 0) {
                            float b[SLOTS2];
                            #pragma unroll
                            for (int k = 0; k < SLOTS2; k++) b[k] = sAct[lane + k * 32];

                            float blo = lo, bhi = hi;
                            #pragma unroll 1
                            for (int it = 0; it < NB; it++) {
                                const float mid = 0.5f * (blo + bhi);
                                float s = 0.0f;
                                #pragma unroll
                                for (int k = 0; k < SLOTS2; k++) s += clipP(b[k] - mid);
                                #pragma unroll
                                for (int o = 16; o > 0; o >>= 1)
                                    s += __shfl_xor_sync(0xffffffffu, s, o);
                                if (C2 + s > BUDGETF) blo = mid; else bhi = mid;
                            }
                            const float tau0 = 0.5f * (blo + bhi);

                            // Newton correction (exact within the linear piece)
                            float gs = 0.0f, cnt = 0.0f;
                            #pragma unroll
                            for (int k = 0; k < SLOTS2; k++) {
                                const float t = b[k] - tau0;
                                gs  += clipP(t);
                                cnt += (t > 0.0f && t < PMAXF) ? 1.0f : 0.0f;
                            }
                            #pragma unroll
                            for (int o = 16; o > 0; o >>= 1) {
                                gs  += __shfl_xor_sync(0xffffffffu, gs, o);
                                cnt += __shfl_xor_sync(0xffffffffu, cnt, o);
                            }
                            if (lane == 0)
                                sTau = tau0 + (C2 + gs - BUDGETF) / fmaxf(cnt, 1.0f);
                        }
                        __syncthreads();
                        tau  = sTau;
                        done = true;
                    }
                }
            }
        }
    }   // v[] dead here

    // ---- feasible rows: output clip(x) (re-read, L1-resident) ----
    if (feas) {
        #pragma unroll
        for (int i = 0; i < VPT / 4; i++) {
            float4 q = rp4[tid + i * THREADS];
            float4 r;
            r.x = clipP(q.x); r.y = clipP(q.y);
            r.z = clipP(q.z); r.w = clipP(q.w);
            op4[tid + i * THREADS] = r;
        }
        return;
    }

    // ---- fallback: full-row bisection streaming from L1 (rare inputs) ----
    if (!done) {
        float vmin = 1e30f, vmax = -1e30f;
        #pragma unroll
        for (int i = 0; i < VPT / 4; i++) {
            float4 q = rp4[tid + i * THREADS];
            vmin = fminf(fminf(vmin, fminf(q.x, q.y)), fminf(q.z, q.w));
            vmax = fmaxf(fmaxf(vmax, fmaxf(q.x, q.y)), fmaxf(q.z, q.w));
        }
        #pragma unroll
        for (int o = 16; o > 0; o >>= 1) {
            vmin = fminf(vmin, __shfl_xor_sync(0xffffffffu, vmin, o));
            vmax = fmaxf(vmax, __shfl_xor_sync(0xffffffffu, vmax, o));
        }
        if (lane == 0) { sP[warp] = vmin; sQ[warp] = vmax; }
        __syncthreads();
        float lo = 1e30f, hi = -1e30f;
        #pragma unroll
        for (int w = 0; w < 8; w++) {
            lo = fminf(lo, sP[w]);
            hi = fmaxf(hi, sQ[w]);
        }
        lo -= PMAXF;

        #pragma unroll 1
        for (int it = 0; it < NFALL; it++) {
            const float mid = 0.5f * (lo + hi);
            float s = 0.0f;
            #pragma unroll
            for (int i = 0; i < VPT / 4; i++) {
                float4 q = rp4[tid + i * THREADS];
                s += clipP(q.x - mid) + clipP(q.y - mid)
                   + clipP(q.z - mid) + clipP(q.w - mid);
            }
            #pragma unroll
            for (int o = 16; o > 0; o >>= 1) s += __shfl_xor_sync(0xffffffffu, s, o);
            const int slot = (it + 1) & 1;
            if (lane == 0) sP[slot * 8 + warp] = s;
            __syncthreads();
            float g = 0.0f;
            #pragma unroll
            for (int w = 0; w < 8; w++) g += sP[slot * 8 + w];
            if (g > BUDGETF) lo = mid; else hi = mid;
        }
        const float tau0 = 0.5f * (lo + hi);

        float gs = 0.0f, cnt = 0.0f;
        #pragma unroll
        for (int i = 0; i < VPT / 4; i++) {
            float4 q = rp4[tid + i * THREADS];
            const float t0 = q.x - tau0, t1 = q.y - tau0, t2 = q.z - tau0, t3 = q.w - tau0;
            gs  += clipP(t0) + clipP(t1) + clipP(t2) + clipP(t3);
            cnt += ((t0 > 0.0f && t0 < PMAXF) ? 1.0f : 0.0f)
                 + ((t1 > 0.0f && t1 < PMAXF) ? 1.0f : 0.0f)
                 + ((t2 > 0.0f && t2 < PMAXF) ? 1.0f : 0.0f)
                 + ((t3 > 0.0f && t3 < PMAXF) ? 1.0f : 0.0f);
        }
        #pragma unroll
        for (int o = 16; o > 0; o >>= 1) {
            gs  += __shfl_xor_sync(0xffffffffu, gs, o);
            cnt += __shfl_xor_sync(0xffffffffu, cnt, o);
        }
        if (lane == 0) { sP[8 + warp] = gs; sQ[8 + warp] = cnt; }
        __syncthreads();
        float gsum = 0.0f, csum = 0.0f;
        #pragma unroll
        for (int w = 0; w < 8; w++) { gsum += sP[8 + w]; csum += sQ[8 + w]; }
        tau = tau0 + (gsum - BUDGETF) / fmaxf(csum, 1.0f);
    }

    // ---- final pass: re-read row (L1-resident) and write projection ----
    #pragma unroll
    for (int i = 0; i < VPT / 4; i++) {
        float4 q = rp4[tid + i * THREADS];
        float4 r;
        r.x = clipP(q.x - tau);
        r.y = clipP(q.y - tau);
        r.z = clipP(q.z - tau);
        r.w = clipP(q.w - tau);
        op4[tid + i * THREADS] = r;
    }
}

extern "C" void kernel_launch(void* const* d_in, const int* in_sizes, int n_in,
                              void* d_out, int out_size) {
    const float* raw = (const float*)d_in[0];
    float*       out = (float*)d_out;
    const int nrows = in_sizes[0] / NLINKS;
    proj_kernel<<<nrows, THREADS>>>(raw, out, nrows);
}

// round 10
// speedup vs baseline: 1.7184x; 1.5159x over previous
#include <cuda_runtime.h>
#include <math.h>

#define NLINKS   4096
#define PMAXF    0.1f
#define BUDGETF  100.0f
#define THREADS  256
#define VPT      16        // 256*16 = 4096
#define PLO      0.56f     // bracket low  (4.1 sigma margin on g(PLO) >= B)
#define PHI      0.73f     // bracket high (4.2 sigma margin on g(PHI) <= B)
#define HB       0.83f     // = PHI + PMAX: x >= HB contributes exactly PMAX on bracket
#define SPLO     5.6f      // scaled bracket (x' = 10x)
#define SPHI     7.3f
#define CAP      416       // band capacity: mean 346, sigma 17.8 -> +4 sigma
#define SLOTSW   13        // CAP/32 regs per warp-0 lane
#define NB       15        // bisection iters: 1.7/2^15 = 5.2e-5 scaled = 5.2e-6 tau
#define NFALL    26        // fallback bisection iters
#define SENT     -1.0e30f

__device__ __forceinline__ float clipP(float t) {
    return fminf(fmaxf(t, 0.0f), PMAXF);
}

__global__ __launch_bounds__(THREADS, 8)
void proj_kernel(const float* __restrict__ raw, float* __restrict__ out, int nrows) {
    __shared__ float sAct[CAP];   // scaled (10x) band values
    __shared__ float sP[16];      // fallback partials (two banks of 8)
    __shared__ float sQ[16];      // cHigh per warp / fallback partials
    __shared__ float sTau;
    __shared__ int   sCnt;
    __shared__ int   sOK;

    const int row = blockIdx.x;
    if (row >= nrows) return;

    const float*  rp  = raw + (size_t)row * NLINKS;
    float*        op  = out + (size_t)row * NLINKS;
    const float4* rp4 = reinterpret_cast<const float4*>(rp);
    float4*       op4 = reinterpret_cast<float4*>(op);

    const int tid  = threadIdx.x;
    const int lane = tid & 31;
    const int warp = tid >> 5;

    if (tid == 0) { sCnt = 0; sOK = 0; }
    // sentinel prefill (ordering vs compaction writes covered by B1)
    sAct[tid] = SENT;
    if (tid < CAP - THREADS) sAct[THREADS + tid] = SENT;

    // ---- pass 1: load row (transient), band predicate + high count ----
    float v[VPT];
    #pragma unroll
    for (int i = 0; i < VPT / 4; i++) {
        float4 q = rp4[tid + i * THREADS];
        v[4*i+0] = q.x; v[4*i+1] = q.y; v[4*i+2] = q.z; v[4*i+3] = q.w;
    }

    int   nact  = 0;
    float cHigh = 0.0f;
    #pragma unroll
    for (int i = 0; i < VPT; i++) {
        const float x = v[i];
        nact  += ((x > PLO) && (x < HB)) ? 1 : 0;
        cHigh += (x >= HB) ? 1.0f : 0.0f;
    }

    __syncthreads();   // B1: orders sCnt/sOK init + sentinels before atomics/writes

    // ---- compaction of band (PLO, HB), stored scaled by 10 ----
    {
        int inc = nact;
        #pragma unroll
        for (int o = 1; o < 32; o <<= 1) {
            int t = __shfl_up_sync(0xffffffffu, inc, o);
            if (lane >= o) inc += t;
        }
        const int excl = inc - nact;
        const int wtot = __shfl_sync(0xffffffffu, inc, 31);
        int wbase = 0;
        if (lane == 0) wbase = atomicAdd(&sCnt, wtot);
        wbase = __shfl_sync(0xffffffffu, wbase, 0);
        int idx = wbase + excl;
        #pragma unroll
        for (int i = 0; i < VPT; i++) {
            const float x = v[i];
            if ((x > PLO) && (x < HB)) {
                if (idx < CAP) sAct[idx] = 10.0f * x;
                idx++;
            }
        }
        // per-warp high count -> smem (summed by warp 0 after B2)
        #pragma unroll
        for (int o = 16; o > 0; o >>= 1)
            cHigh += __shfl_xor_sync(0xffffffffu, cHigh, o);
        if (lane == 0) sQ[warp] = cHigh;
    }
    __syncthreads();   // B2
    const int nAct = sCnt;

    // ---- warp-0-only solve: verify bracket, bisect, Newton ----
    if (nAct <= CAP && warp == 0) {
        float b[SLOTSW];
        #pragma unroll
        for (int k = 0; k < SLOTSW; k++) b[k] = sAct[lane + k * 32];

        float Ch = 0.0f;
        #pragma unroll
        for (int w = 0; w < 8; w++) Ch += sQ[w];
        const float Bs = 1000.0f - Ch;   // scaled budget: B/PMAX - n_high

        // bracket verification: g'(SPLO) >= Bs >= g'(SPHI)
        float gL = 0.0f, gH = 0.0f;
        #pragma unroll
        for (int k = 0; k < SLOTSW; k++) {
            gL += __saturatef(b[k] - SPLO);
            gH += __saturatef(b[k] - SPHI);
        }
        #pragma unroll
        for (int o = 16; o > 0; o >>= 1) {
            gL += __shfl_xor_sync(0xffffffffu, gL, o);
            gH += __shfl_xor_sync(0xffffffffu, gH, o);
        }

        if (gL >= Bs && gH <= Bs) {
            float lo = SPLO, hi = SPHI;
            #pragma unroll 1
            for (int it = 0; it < NB; it++) {
                const float mid = 0.5f * (lo + hi);
                float s = 0.0f;
                #pragma unroll
                for (int k = 0; k < SLOTSW; k++) s += __saturatef(b[k] - mid);
                #pragma unroll
                for (int o = 16; o > 0; o >>= 1)
                    s += __shfl_xor_sync(0xffffffffu, s, o);
                if (s > Bs) lo = mid; else hi = mid;
            }
            const float tau0 = 0.5f * (lo + hi);

            // Newton / implicit-function correction (exact within linear piece)
            float gs = 0.0f, cnt = 0.0f;
            #pragma unroll
            for (int k = 0; k < SLOTSW; k++) {
                const float t = b[k] - tau0;
                gs  += __saturatef(t);
                cnt += (t > 0.0f && t < 1.0f) ? 1.0f : 0.0f;
            }
            #pragma unroll
            for (int o = 16; o > 0; o >>= 1) {
                gs  += __shfl_xor_sync(0xffffffffu, gs, o);
                cnt += __shfl_xor_sync(0xffffffffu, cnt, o);
            }
            if (lane == 0) {
                sTau = PMAXF * (tau0 + (gs - Bs) / fmaxf(cnt, 1.0f));
                sOK  = 1;
            }
        }
    }
    __syncthreads();   // B3

    float tau = 0.0f;

    if (sOK) {
        tau = sTau;
    } else {
        // ---- fallback: feasible rows + adversarial inputs (rare) ----
        // feasibility: g(0) <= B ?
        float s0 = 0.0f;
        #pragma unroll
        for (int i = 0; i < VPT; i++) s0 += clipP(v[i]);
        float vmin = 1e30f, vmax = -1e30f;
        #pragma unroll
        for (int i = 0; i < VPT; i++) {
            vmin = fminf(vmin, v[i]);
            vmax = fmaxf(vmax, v[i]);
        }
        #pragma unroll
        for (int o = 16; o > 0; o >>= 1) {
            s0   += __shfl_xor_sync(0xffffffffu, s0, o);
            vmin  = fminf(vmin, __shfl_xor_sync(0xffffffffu, vmin, o));
            vmax  = fmaxf(vmax, __shfl_xor_sync(0xffffffffu, vmax, o));
        }
        if (lane == 0) { sP[warp] = s0; sP[8 + warp] = vmin; sQ[warp] = vmax; }
        __syncthreads();
        float g0 = 0.0f, lo = 1e30f, hi = -1e30f;
        #pragma unroll
        for (int w = 0; w < 8; w++) {
            g0 += sP[w];
            lo  = fminf(lo, sP[8 + w]);
            hi  = fmaxf(hi, sQ[w]);
        }
        lo -= PMAXF;

        if (g0 <= BUDGETF) {
            // feasible: clip(x) is the answer (tau = 0)
            #pragma unroll
            for (int i = 0; i < VPT / 4; i++) {
                float4 q = rp4[tid + i * THREADS];
                float4 r;
                r.x = clipP(q.x); r.y = clipP(q.y);
                r.z = clipP(q.z); r.w = clipP(q.w);
                op4[tid + i * THREADS] = r;
            }
            return;
        }

        __syncthreads();   // protect sP/sQ reuse below vs reads above
        #pragma unroll 1
        for (int it = 0; it < NFALL; it++) {
            const float mid = 0.5f * (lo + hi);
            float s = 0.0f;
            #pragma unroll
            for (int i = 0; i < VPT; i++) s += clipP(v[i] - mid);
            #pragma unroll
            for (int o = 16; o > 0; o >>= 1) s += __shfl_xor_sync(0xffffffffu, s, o);
            const int slot = it & 1;
            if (lane == 0) sP[slot * 8 + warp] = s;
            __syncthreads();
            float g = 0.0f;
            #pragma unroll
            for (int w = 0; w < 8; w++) g += sP[slot * 8 + w];
            if (g > BUDGETF) lo = mid; else hi = mid;
        }
        const float tau0 = 0.5f * (lo + hi);

        float gs = 0.0f, cnt = 0.0f;
        #pragma unroll
        for (int i = 0; i < VPT; i++) {
            const float t = v[i] - tau0;
            gs  += clipP(t);
            cnt += (t > 0.0f && t < PMAXF) ? 1.0f : 0.0f;
        }
        #pragma unroll
        for (int o = 16; o > 0; o >>= 1) {
            gs  += __shfl_xor_sync(0xffffffffu, gs, o);
            cnt += __shfl_xor_sync(0xffffffffu, cnt, o);
        }
        if (lane == 0) { sQ[8 + warp] = gs; sQ[warp] = cnt; }
        __syncthreads();
        float gsum = 0.0f, csum = 0.0f;
        #pragma unroll
        for (int w = 0; w < 8; w++) { gsum += sQ[8 + w]; csum += sQ[w]; }
        tau = tau0 + (gsum - BUDGETF) / fmaxf(csum, 1.0f);
    }

    // ---- final pass: re-read row (L1-resident) and write projection ----
    #pragma unroll
    for (int i = 0; i < VPT / 4; i++) {
        float4 q = rp4[tid + i * THREADS];
        float4 r;
        r.x = clipP(q.x - tau);
        r.y = clipP(q.y - tau);
        r.z = clipP(q.z - tau);
        r.w = clipP(q.w - tau);
        op4[tid + i * THREADS] = r;
    }
}

extern "C" void kernel_launch(void* const* d_in, const int* in_sizes, int n_in,
                              void* d_out, int out_size) {
    const float* raw = (const float*)d_in[0];
    float*       out = (float*)d_out;
    const int nrows = in_sizes[0] / NLINKS;
    proj_kernel<<<nrows, THREADS>>>(raw, out, nrows);
}